// round 15
// baseline (speedup 1.0000x reference)
#include <cuda_runtime.h>
#include <math.h>

// ---------------------------------------------------------------------------
// Angular spectrum propagation, W=3, B=2, N=2048, double-float (f32 pair).
// R15: (1) full 2048-entry stage-1 twiddle table (no wrap select/negation),
// (2) cmulc_conj for inverse twiddles (bit-identical, fewer ops),
// (3) global loads issued before tw staging+barrier (latency overlap),
// (4) merged init kernel. Rest identical to R14: Dekker fast2sum dd,
// XS swizzle, swizzled tw23, warp-local barrier demotion, digit-reversed
// spectrum, bit-matched f32 H args, fast_atan2 epilogue, soft +/-pi decision.
// ---------------------------------------------------------------------------

#define NF    2048
#define L2N   11
#define NIMG  6
#define IMG_ELEMS ((size_t)NF * NF)
#define OUT_HALF ((size_t)NIMG * NF * NF)

static __device__ float4 g_spec[(size_t)NIMG * NF * NF];
static __device__ float4 g_tw4[2048];
static __device__ float4 g_tw23[288];   // [0,256): stage-2  [256,288): stage-3

__constant__ float c_lam[3] = {4.0e-7f, 5.32e-7f, 7.0e-7f};

// ------------------------------ pair arithmetic ----------------------------
struct __align__(8)  dd  { float hi, lo; };
struct __align__(16) ddc { dd re, im; };

// Dekker fast2sum with magnitude select; lo-term reassociated.
__device__ __forceinline__ dd padd(dd a, dd b) {
    float s  = a.hi + b.hi;
    float bg = (fabsf(a.hi) >= fabsf(b.hi)) ? a.hi : b.hi;
    float sm = (fabsf(a.hi) >= fabsf(b.hi)) ? b.hi : a.hi;
    float e  = sm - (s - bg);
    dd r; r.hi = s; r.lo = e + (a.lo + b.lo); return r;
}
__device__ __forceinline__ dd psub(dd a, dd b) {
    float nbh = -b.hi;
    float s  = a.hi + nbh;
    float bg = (fabsf(a.hi) >= fabsf(nbh)) ? a.hi : nbh;
    float sm = (fabsf(a.hi) >= fabsf(nbh)) ? nbh : a.hi;
    float e  = sm - (s - bg);
    dd r; r.hi = s; r.lo = e + (a.lo - b.lo); return r;
}
__device__ __forceinline__ dd pmul(dd a, dd b) {
    float p = a.hi * b.hi;
    float e = fmaf(a.hi, b.hi, -p);
    e = fmaf(a.hi, b.lo, e);
    e = fmaf(a.lo, b.hi, e);
    dd r; r.hi = p; r.lo = e; return r;
}
__device__ __forceinline__ dd pmuls(dd a, float s) {
    float p = a.hi * s;
    float e = fmaf(a.hi, s, -p);
    e = fmaf(a.lo, s, e);
    dd r; r.hi = p; r.lo = e; return r;
}
__device__ __forceinline__ dd negdd(dd a) { dd r; r.hi = -a.hi; r.lo = -a.lo; return r; }

__device__ __forceinline__ ddc cadd(ddc a, ddc b) { ddc r; r.re = padd(a.re,b.re); r.im = padd(a.im,b.im); return r; }
__device__ __forceinline__ ddc csub(ddc a, ddc b) { ddc r; r.re = psub(a.re,b.re); r.im = psub(a.im,b.im); return r; }
__device__ __forceinline__ ddc cmulc(ddc a, ddc b) {        // a * b
    ddc r;
    r.re = psub(pmul(a.re,b.re), pmul(a.im,b.im));
    r.im = padd(pmul(a.re,b.im), pmul(a.im,b.re));
    return r;
}
__device__ __forceinline__ ddc cmulc_conj(ddc a, ddc b) {   // a * conj(b)
    ddc r;
    r.re = padd(pmul(a.re,b.re), pmul(a.im,b.im));
    r.im = psub(pmul(a.im,b.re), pmul(a.re,b.im));
    return r;
}
__device__ __forceinline__ ddc f4_to_ddc(float4 v) { ddc r; r.re.hi=v.x; r.re.lo=v.y; r.im.hi=v.z; r.im.lo=v.w; return r; }
__device__ __forceinline__ float4 ddc_to_f4(ddc v) { return make_float4(v.re.hi, v.re.lo, v.im.hi, v.im.lo); }

// sqrt(2)/2 as a dd constant
#define RT2H 0.70710678118654752440f
#define RT2L 1.2101617104e-08f
__device__ __forceinline__ dd pmulC(dd a) {
    dd c; c.hi = RT2H; c.lo = RT2L;
    return pmul(a, c);
}

// ------------------- pair-precision exp(+i*ph) for f32 ph -------------------
__device__ __forceinline__ ddc psincos(float ph, const ddc* __restrict__ tw) {
    const float PH_ = (float)(M_PI / 1024.0);
    const float PL_ = (float)(M_PI / 1024.0 - (double)((float)(M_PI / 1024.0)));
    int   m  = __float2int_rn(ph * 325.9493234522017f);   // 1024/pi
    float fm = (float)m;
    float th = fm * PH_;
    float te = fmaf(fm, PH_, -th);
    float tl = fmaf(fm, PL_, te);
    float s  = ph - th;
    float bb = s - ph;
    float e  = (ph - (s - bb)) + ((-th) - bb);
    float dl = e - tl;
    float dh = s + dl;
    dl = dl - (dh - s);
    float d2 = dh * dh;
    dd sd; sd.hi = dh;   sd.lo = fmaf(d2 * dh, -(1.0f/6.0f), dl);
    dd cd; cd.hi = 1.0f; cd.lo = -0.5f * d2;
    unsigned k = ((unsigned)(-m)) & 2047u;
    ddc w = tw[k];                       // full 2048-entry table, no wrap
    ddc r;
    r.re = psub(pmul(w.re, cd), pmul(w.im, sd));
    r.im = padd(pmul(w.re, sd), pmul(w.im, cd));
    return r;
}

// --------------------- fast atan2 (max err ~2e-5 rad) -----------------------
__device__ __forceinline__ float fast_atan2(float y, float x) {
    float ax = fabsf(x), ay = fabsf(y);
    float mx = fmaxf(ax, ay), mn = fminf(ax, ay);
    float t  = (mx > 0.0f) ? __fdividef(mn, mx) : 0.0f;
    float t2 = t * t;
    float p = -0.01172120f;
    p = fmaf(p, t2,  0.05265332f);
    p = fmaf(p, t2, -0.11643287f);
    p = fmaf(p, t2,  0.19354346f);
    p = fmaf(p, t2, -0.33262347f);
    p = fmaf(p, t2,  0.99997726f);
    float r = p * t;
    if (ay > ax)  r = 1.57079632679489662f - r;
    if (x < 0.0f) r = 3.14159265358979323f - r;
    return copysignf(r, y);
}

// ------------------------------ smem addressing -----------------------------
__device__ __forceinline__ int XS(int i) { return i ^ ((i >> 3) & 7); }
#define BUFSZ 2048
#define TWN   2048

// reversed-address -> true frequency: a = 4g+f holds S[512f + h(g)]
__device__ __forceinline__ int freq_of(int a) {
    const int g = a >> 2, f = a & 3;
    return 512 * f + 64 * (g & 7) + 8 * ((g >> 3) & 7) + (g >> 6);
}

// ------------------------------ FFT primitives ------------------------------
template<int INV>
__device__ __forceinline__ ddc rotmi(ddc a) {   // fwd: *(-i)  inv: *(+i)
    ddc r;
    if (!INV) { r.re = a.im;        r.im = negdd(a.re); }
    else      { r.re = negdd(a.im); r.im = a.re; }
    return r;
}
template<int INV>
__device__ __forceinline__ ddc w81m(ddc a) {
    dd p = padd(a.re, a.im);
    dd m = psub(a.im, a.re);
    ddc r;
    if (!INV) { r.re = pmulC(p);         r.im = pmulC(m); }
    else      { r.re = negdd(pmulC(m));  r.im = pmulC(p); }
    return r;
}
template<int INV>
__device__ __forceinline__ ddc w83m(ddc a) {
    dd p = padd(a.re, a.im);
    dd m = psub(a.im, a.re);
    ddc r;
    if (!INV) { r.re = pmulC(m);         r.im = negdd(pmulC(p)); }
    else      { r.re = negdd(pmulC(p));  r.im = negdd(pmulC(m)); }
    return r;
}

template<int INV>
__device__ __forceinline__ void dft8(ddc* x) {
    ddc t0 = cadd(x[0], x[4]);
    ddc t1 = csub(x[0], x[4]);
    ddc t2 = cadd(x[2], x[6]);
    ddc t3 = csub(x[2], x[6]);
    ddc r3 = rotmi<INV>(t3);
    ddc E0 = cadd(t0, t2);
    ddc E2 = csub(t0, t2);
    ddc E1 = cadd(t1, r3);
    ddc E3 = csub(t1, r3);
    ddc u0 = cadd(x[1], x[5]);
    ddc u1 = csub(x[1], x[5]);
    ddc u2 = cadd(x[3], x[7]);
    ddc u3 = csub(x[3], x[7]);
    ddc s3 = rotmi<INV>(u3);
    ddc O0 = cadd(u0, u2);
    ddc O2 = csub(u0, u2);
    ddc O1 = cadd(u1, s3);
    ddc O3 = csub(u1, s3);
    ddc O1r = w81m<INV>(O1);
    ddc O2r = rotmi<INV>(O2);
    ddc O3r = w83m<INV>(O3);
    x[0] = cadd(E0, O0);  x[4] = csub(E0, O0);
    x[1] = cadd(E1, O1r); x[5] = csub(E1, O1r);
    x[2] = cadd(E2, O2r); x[6] = csub(E2, O2r);
    x[3] = cadd(E3, O3r); x[7] = csub(E3, O3r);
}

// stage-1 twiddles: full 2048 table, direct index; INV via conj multiply
template<int INV>
__device__ __forceinline__ void tw_apply1(ddc* x, const ddc* __restrict__ tw, int tt) {
    int idx = 0;
    #pragma unroll
    for (int j = 1; j < 8; ++j) {
        idx += tt;                       // idx = tt*j < 2048 always
        ddc w = tw[idx];
        x[j] = INV ? cmulc_conj(x[j], w) : cmulc(x[j], w);
    }
}
// stage-2/3 twiddles: dedicated swizzled table; INV via conj multiply
template<int INV, int BASE>
__device__ __forceinline__ void tw_apply23(ddc* x, const ddc* __restrict__ tw23, int t) {
    #pragma unroll
    for (int j = 1; j < 8; ++j) {
        ddc w = tw23[BASE + XS(t * 8 + j)];
        x[j] = INV ? cmulc_conj(x[j], w) : cmulc(x[j], w);
    }
}

// Forward DIF stages 1-3, IN-PLACE in A (XS-swizzled addresses).
__device__ __forceinline__ void fwd_stages123(ddc* x, const ddc* __restrict__ tw,
                                              const ddc* __restrict__ tw23,
                                              ddc* A, int tt) {
    dft8<0>(x);
    tw_apply1<0>(x, tw, tt);
    #pragma unroll
    for (int j = 0; j < 8; ++j) A[XS(j * 256 + tt)] = x[j];
    __syncthreads();                    // inter-warp exchange

    const int j1 = tt >> 5, t2 = tt & 31;
    #pragma unroll
    for (int k = 0; k < 8; ++k) x[k] = A[XS(j1 * 256 + t2 + 32 * k)];
    dft8<0>(x);
    tw_apply23<0, 0>(x, tw23, t2);
    #pragma unroll
    for (int j = 0; j < 8; ++j) A[XS(j1 * 256 + j * 32 + t2)] = x[j];
    __syncwarp();                       // intra-warp exchange

    const int j2 = (tt >> 2) & 7, t3 = tt & 3;
    #pragma unroll
    for (int k = 0; k < 8; ++k) x[k] = A[XS(j1 * 256 + j2 * 32 + t3 + 4 * k)];
    dft8<0>(x);
    tw_apply23<0, 256>(x, tw23, t3);
    #pragma unroll
    for (int j = 0; j < 8; ++j) A[XS(j1 * 256 + j2 * 32 + j * 4 + t3)] = x[j];
    __syncwarp();                       // intra-warp exchange
}

// Transposed-DIT inverse stages 3',2',1', IN-PLACE in A.
__device__ __forceinline__ void inv_stages321(ddc* x, const ddc* __restrict__ tw,
                                              const ddc* __restrict__ tw23,
                                              ddc* A, int tt) {
    const int j1 = tt >> 5, t2 = tt & 31;
    const int j2 = (tt >> 2) & 7, t3 = tt & 3;

    #pragma unroll
    for (int j = 0; j < 8; ++j) x[j] = A[XS(j1 * 256 + j2 * 32 + 4 * j + t3)];
    tw_apply23<1, 256>(x, tw23, t3);     // conj twiddle BEFORE butterfly
    dft8<1>(x);
    #pragma unroll
    for (int k = 0; k < 8; ++k) A[XS(j1 * 256 + j2 * 32 + t3 + 4 * k)] = x[k];
    __syncwarp();                        // intra-warp exchange

    #pragma unroll
    for (int j = 0; j < 8; ++j) x[j] = A[XS(j1 * 256 + 32 * j + t2)];
    tw_apply23<1, 0>(x, tw23, t2);
    dft8<1>(x);
    #pragma unroll
    for (int k = 0; k < 8; ++k) A[XS(j1 * 256 + t2 + 32 * k)] = x[k];
    __syncthreads();                     // inter-warp exchange

    #pragma unroll
    for (int j = 0; j < 8; ++j) x[j] = A[XS(256 * j + tt)];
    tw_apply1<1>(x, tw, tt);
    dft8<1>(x);
    // x[k] = out[tt + 256k]
}

// ------------------------------ init twiddles (merged) ----------------------
__global__ void k_init(void) {
    int e = blockIdx.x * 32 + threadIdx.x;   // 73 blocks x 32 = 2336
    if (e < 2048) {
        double s, c;
        sincospi(-(double)e / 1024.0, &s, &c);
        float ch = (float)c, cl = (float)(c - (double)ch);
        float sh = (float)s, sl = (float)(s - (double)sh);
        g_tw4[e] = make_float4(ch, cl, sh, sl);
    } else if (e < 2336) {
        int e2 = e - 2048;
        double ang;
        int slot;
        if (e2 < 256) {          // stage 2: w = exp(-2pi*i*(8*t2*j)/2048)
            int t2 = e2 >> 3, j = e2 & 7;
            ang  = (double)(t2 * j) / 128.0;
            slot = XS(e2);
        } else {                 // stage 3: w = exp(-2pi*i*(64*t3*j)/2048)
            int e3 = e2 - 256;
            int t3 = e3 >> 3, j = e3 & 7;
            ang  = (double)(t3 * j) / 16.0;
            slot = 256 + XS(e3);
        }
        double s, c;
        sincospi(-ang, &s, &c);
        float ch = (float)c, cl = (float)(c - (double)ch);
        float sh = (float)s, sl = (float)(s - (double)sh);
        g_tw23[slot] = make_float4(ch, cl, sh, sl);
    }
}

// --------------------------- shared tw staging ------------------------------
__device__ __forceinline__ void stage_tw(ddc* tw, ddc* tw23, int tt) {
    #pragma unroll
    for (int i = tt; i < TWN; i += 256) tw[i] = f4_to_ddc(g_tw4[i]);
    if (tt < 32)  tw23[256 + tt] = f4_to_ddc(g_tw23[256 + tt]);
    if (tt < 256) tw23[tt]       = f4_to_ddc(g_tw23[tt]);
}

// --------------------------- Kernel 1: rows forward (DIF) -------------------
__global__ void __launch_bounds__(256, 3)
k_fwd_rows(const float* __restrict__ amp,
           const float* __restrict__ phs,
           const float* __restrict__ aper) {
    extern __shared__ ddc sh[];
    ddc* tw   = sh;              // 2048
    ddc* tw23 = sh + TWN;        // 288
    ddc* A    = sh + TWN + 288;  // BUFSZ

    const int tt  = threadIdx.x;
    const int row = blockIdx.x & (NF - 1);
    const int img = blockIdx.x >> L2N;
    const size_t base = (size_t)img * IMG_ELEMS + ((size_t)row << L2N);

    // issue global loads FIRST (latency overlaps tw staging + barrier)
    float av[8], pv[8];
    #pragma unroll
    for (int k = 0; k < 8; ++k) {
        const int i = tt + 256 * k;
        av[k] = __fmul_rn(amp[base + i], aper[((size_t)row << L2N) + i]);
        pv[k] = phs[base + i];
    }

    stage_tw(tw, tw23, tt);
    __syncthreads();

    ddc x[8];
    #pragma unroll
    for (int k = 0; k < 8; ++k) {
        ddc e = psincos(pv[k], tw);
        x[k].re = pmuls(e.re, av[k]);
        x[k].im = pmuls(e.im, av[k]);
    }

    fwd_stages123(x, tw, tw23, A, tt);

    // stage 4 in registers, direct coalesced write in reversed order
    #pragma unroll
    for (int gg = 0; gg < 2; ++gg) {
        const int g = 2 * tt + gg;
        ddc a = A[XS(4 * g + 0)];
        ddc b = A[XS(4 * g + 1)];
        ddc c = A[XS(4 * g + 2)];
        ddc d = A[XS(4 * g + 3)];
        ddc t0 = cadd(a, c), t1 = csub(a, c);
        ddc t2 = cadd(b, d), t3 = csub(b, d);
        ddc r  = rotmi<0>(t3);
        g_spec[base + 4 * g + 0] = ddc_to_f4(cadd(t0, t2));
        g_spec[base + 4 * g + 1] = ddc_to_f4(cadd(t1, r));
        g_spec[base + 4 * g + 2] = ddc_to_f4(csub(t0, t2));
        g_spec[base + 4 * g + 3] = ddc_to_f4(csub(t1, r));
    }
}

// ------------------- Kernel 2: cols DIF + H + transposed-DIT ----------------
__global__ void __launch_bounds__(256, 3)
k_cols() {
    extern __shared__ ddc sh[];
    ddc* tw   = sh;
    ddc* tw23 = sh + TWN;
    ddc* A    = sh + TWN + 288;

    const int tt  = threadIdx.x;
    const int img = blockIdx.x >> L2N;
    const int col = blockIdx.x & (NF - 1);   // ADDRESS in permuted-x layout
    const size_t ibase = (size_t)img * IMG_ELEMS;

    // issue (uncoalesced) column loads FIRST
    ddc x[8];
    #pragma unroll
    for (int k = 0; k < 8; ++k)
        x[k] = f4_to_ddc(g_spec[ibase + ((size_t)(tt + 256 * k) << L2N) + col]);

    stage_tw(tw, tw23, tt);
    __syncthreads();

    fwd_stages123(x, tw, tw23, A, tt);

    // ---- stage 4 fwd + H + stage 4' inverse, in registers (own-warp cells) ----
    const int   w    = img >> 1;
    const float lam  = c_lam[w];
    const float lam2 = __fmul_rn(lam, lam);
    const float cov  = __fdiv_rn(6.283185307179586f, lam);
    const float DF   = 488.28125f;
    const int   cfr  = freq_of(col);                 // true kx frequency
    const int   kx   = (cfr < 1024) ? cfr : cfr - 2048;
    const float fx   = (float)kx * DF;
    const float fx2  = __fmul_rn(fx, fx);

    #pragma unroll
    for (int gg = 0; gg < 2; ++gg) {
        const int g = 2 * tt + gg;
        const int h = 64 * (g & 7) + 8 * ((g >> 3) & 7) + (g >> 6);
        ddc a = A[XS(4 * g + 0)];
        ddc b = A[XS(4 * g + 1)];
        ddc c = A[XS(4 * g + 2)];
        ddc d = A[XS(4 * g + 3)];
        ddc t0 = cadd(a, c), t1 = csub(a, c);
        ddc t2 = cadd(b, d), t3 = csub(b, d);
        ddc r  = rotmi<0>(t3);
        ddc F[4];
        F[0] = cadd(t0, t2);
        F[1] = cadd(t1, r);
        F[2] = csub(t0, t2);
        F[3] = csub(t1, r);
        #pragma unroll
        for (int f = 0; f < 4; ++f) {
            const int m  = 512 * f + h;
            const int ky = (m < 1024) ? m : m - 2048;
            const float fy  = (float)ky * DF;
            const float f2  = __fadd_rn(__fmul_rn(fy, fy), fx2);
            const float arg = __fsub_rn(1.0f, __fmul_rn(lam2, f2));
            if (arg > 0.0f) {
                const float kz = __fmul_rn(cov, __fsqrt_rn(arg));
                const float ph = __fmul_rn(kz, 1.0e-3f);
                ddc H = psincos(ph, tw);
                F[f] = cmulc(F[f], H);
            } else {
                F[f].re.hi = F[f].re.lo = F[f].im.hi = F[f].im.lo = 0.0f;
            }
        }
        // inverse radix-4 (stage 4'), write back to the SAME cells
        ddc s0 = cadd(F[0], F[2]), s1 = csub(F[0], F[2]);
        ddc s2 = cadd(F[1], F[3]), s3 = csub(F[1], F[3]);
        ddc ri = rotmi<1>(s3);
        A[XS(4 * g + 0)] = cadd(s0, s2);
        A[XS(4 * g + 1)] = cadd(s1, ri);
        A[XS(4 * g + 2)] = csub(s0, s2);
        A[XS(4 * g + 3)] = csub(s1, ri);
    }
    __syncwarp();                       // H-stage exchange is intra-warp

    inv_stages321(x, tw, tw23, A, tt);

    #pragma unroll
    for (int k = 0; k < 8; ++k)
        g_spec[ibase + ((size_t)(tt + 256 * k) << L2N) + col] = ddc_to_f4(x[k]);
}

// --------------------------- Kernel 3: rows inverse (DIT) -------------------
__global__ void __launch_bounds__(256, 3)
k_inv_rows(float* __restrict__ out) {
    extern __shared__ ddc sh[];
    ddc* tw   = sh;
    ddc* tw23 = sh + TWN;
    ddc* A    = sh + TWN + 288;

    const int tt  = threadIdx.x;
    const int row = blockIdx.x & (NF - 1);
    const int img = blockIdx.x >> L2N;
    const size_t base = (size_t)img * IMG_ELEMS + ((size_t)row << L2N);

    // issue coalesced spectrum loads FIRST (8tt..8tt+7)
    float4 Fv[8];
    #pragma unroll
    for (int q = 0; q < 8; ++q) Fv[q] = g_spec[base + 8 * tt + q];

    stage_tw(tw, tw23, tt);
    __syncthreads();

    // stage 4' : inv radix-4 on the prefetched reversed-order spectrum
    #pragma unroll
    for (int gg = 0; gg < 2; ++gg) {
        const int g = 2 * tt + gg;
        ddc F0 = f4_to_ddc(Fv[4 * gg + 0]);
        ddc F1 = f4_to_ddc(Fv[4 * gg + 1]);
        ddc F2 = f4_to_ddc(Fv[4 * gg + 2]);
        ddc F3 = f4_to_ddc(Fv[4 * gg + 3]);
        ddc s0 = cadd(F0, F2), s1 = csub(F0, F2);
        ddc s2 = cadd(F1, F3), s3 = csub(F1, F3);
        ddc ri = rotmi<1>(s3);
        A[XS(4 * g + 0)] = cadd(s0, s2);
        A[XS(4 * g + 1)] = cadd(s1, ri);
        A[XS(4 * g + 2)] = csub(s0, s2);
        A[XS(4 * g + 3)] = csub(s1, ri);
    }
    __syncwarp();

    ddc x[8];
    inv_stages321(x, tw, tw23, A, tt);

    const float sc = 1.0f / 4194304.0f;   // 1/N^2 = 2^-22 exact
    #pragma unroll
    for (int k = 0; k < 8; ++k) {
        const int n = tt + 256 * k;
        ddc v = x[k];
        float re = (v.re.hi + v.re.lo) * sc;
        float im = (v.im.hi + v.im.lo) * sc;
        out[base + n] = __fsqrt_rn(re * re + im * im);
        float ang;
        if (re < -1.0e-6f && fabsf(im) < 1.0e-6f) {
            ang = erff(im * 1.2627e7f) * 3.14159274f;  // soft +/-pi decision
        } else {
            ang = fast_atan2(im, re);
        }
        out[OUT_HALF + base + n] = ang;
    }
}

// ---------------------------------------------------------------------------
extern "C" void kernel_launch(void* const* d_in, const int* in_sizes, int n_in,
                              void* d_out, int out_size) {
    const float* amp = (const float*)d_in[0];
    const float* phs = (const float*)d_in[1];
    const float* ap  = (const float*)d_in[2];
    float* out = (float*)d_out;

    const int smem_sz = (TWN + 288 + BUFSZ) * (int)sizeof(ddc);   // 70144 B
    cudaFuncSetAttribute(k_fwd_rows, cudaFuncAttributeMaxDynamicSharedMemorySize, smem_sz);
    cudaFuncSetAttribute(k_cols,     cudaFuncAttributeMaxDynamicSharedMemorySize, smem_sz);
    cudaFuncSetAttribute(k_inv_rows, cudaFuncAttributeMaxDynamicSharedMemorySize, smem_sz);

    k_init<<<73, 32>>>();
    k_fwd_rows<<<NIMG * NF, 256, smem_sz>>>(amp, phs, ap);
    k_cols<<<NIMG * NF, 256, smem_sz>>>();
    k_inv_rows<<<NIMG * NF, 256, smem_sz>>>(out);
}

// round 16
// speedup vs baseline: 1.1922x; 1.1922x over previous
#include <cuda_runtime.h>
#include <math.h>

// ---------------------------------------------------------------------------
// Angular spectrum propagation, W=3, B=2, N=2048, double-float (f32 pair).
// R16: R14 base (1024-entry tw table, 53.7KB smem, 3 blocks/SM) plus ONLY the
// verified R15 winners: (a) k_inv coalesced spectrum prefetch before tw
// staging, (b) k_fwd coalesced input prefetch, (c) cmulc_conj for inverse
// twiddles (conj commutes with wrap negation -> bit-identical, fewer ops).
// k_cols restored to R14 exactly (uncoalesced loads AFTER the barrier — the
// R15 early-load variant flooded the L1tex queue and regressed 300us).
// ---------------------------------------------------------------------------

#define NF    2048
#define L2N   11
#define NIMG  6
#define IMG_ELEMS ((size_t)NF * NF)
#define OUT_HALF ((size_t)NIMG * NF * NF)

static __device__ float4 g_spec[(size_t)NIMG * NF * NF];
static __device__ float4 g_tw4[1024];
static __device__ float4 g_tw23[288];   // [0,256): stage-2  [256,288): stage-3

__constant__ float c_lam[3] = {4.0e-7f, 5.32e-7f, 7.0e-7f};

// ------------------------------ pair arithmetic ----------------------------
struct __align__(8)  dd  { float hi, lo; };
struct __align__(16) ddc { dd re, im; };

__device__ __forceinline__ dd padd(dd a, dd b) {
    float s  = a.hi + b.hi;
    float bg = (fabsf(a.hi) >= fabsf(b.hi)) ? a.hi : b.hi;
    float sm = (fabsf(a.hi) >= fabsf(b.hi)) ? b.hi : a.hi;
    float e  = sm - (s - bg);
    dd r; r.hi = s; r.lo = e + (a.lo + b.lo); return r;
}
__device__ __forceinline__ dd psub(dd a, dd b) {
    float nbh = -b.hi;
    float s  = a.hi + nbh;
    float bg = (fabsf(a.hi) >= fabsf(nbh)) ? a.hi : nbh;
    float sm = (fabsf(a.hi) >= fabsf(nbh)) ? nbh : a.hi;
    float e  = sm - (s - bg);
    dd r; r.hi = s; r.lo = e + (a.lo - b.lo); return r;
}
__device__ __forceinline__ dd pmul(dd a, dd b) {
    float p = a.hi * b.hi;
    float e = fmaf(a.hi, b.hi, -p);
    e = fmaf(a.hi, b.lo, e);
    e = fmaf(a.lo, b.hi, e);
    dd r; r.hi = p; r.lo = e; return r;
}
__device__ __forceinline__ dd pmuls(dd a, float s) {
    float p = a.hi * s;
    float e = fmaf(a.hi, s, -p);
    e = fmaf(a.lo, s, e);
    dd r; r.hi = p; r.lo = e; return r;
}
__device__ __forceinline__ dd negdd(dd a) { dd r; r.hi = -a.hi; r.lo = -a.lo; return r; }

__device__ __forceinline__ ddc cadd(ddc a, ddc b) { ddc r; r.re = padd(a.re,b.re); r.im = padd(a.im,b.im); return r; }
__device__ __forceinline__ ddc csub(ddc a, ddc b) { ddc r; r.re = psub(a.re,b.re); r.im = psub(a.im,b.im); return r; }
__device__ __forceinline__ ddc cmulc(ddc a, ddc b) {        // a * b
    ddc r;
    r.re = psub(pmul(a.re,b.re), pmul(a.im,b.im));
    r.im = padd(pmul(a.re,b.im), pmul(a.im,b.re));
    return r;
}
__device__ __forceinline__ ddc cmulc_conj(ddc a, ddc b) {   // a * conj(b)
    ddc r;
    r.re = padd(pmul(a.re,b.re), pmul(a.im,b.im));
    r.im = psub(pmul(a.im,b.re), pmul(a.re,b.im));
    return r;
}
__device__ __forceinline__ ddc cneg(ddc a) { ddc r; r.re = negdd(a.re); r.im = negdd(a.im); return r; }
__device__ __forceinline__ ddc f4_to_ddc(float4 v) { ddc r; r.re.hi=v.x; r.re.lo=v.y; r.im.hi=v.z; r.im.lo=v.w; return r; }
__device__ __forceinline__ float4 ddc_to_f4(ddc v) { return make_float4(v.re.hi, v.re.lo, v.im.hi, v.im.lo); }

// sqrt(2)/2 as a dd constant
#define RT2H 0.70710678118654752440f
#define RT2L 1.2101617104e-08f
__device__ __forceinline__ dd pmulC(dd a) {
    dd c; c.hi = RT2H; c.lo = RT2L;
    return pmul(a, c);
}

// ------------------- pair-precision exp(+i*ph) for f32 ph -------------------
__device__ __forceinline__ ddc psincos(float ph, const ddc* __restrict__ tw) {
    const float PH_ = (float)(M_PI / 1024.0);
    const float PL_ = (float)(M_PI / 1024.0 - (double)((float)(M_PI / 1024.0)));
    int   m  = __float2int_rn(ph * 325.9493234522017f);   // 1024/pi
    float fm = (float)m;
    float th = fm * PH_;
    float te = fmaf(fm, PH_, -th);
    float tl = fmaf(fm, PL_, te);
    float s  = ph - th;
    float bb = s - ph;
    float e  = (ph - (s - bb)) + ((-th) - bb);
    float dl = e - tl;
    float dh = s + dl;
    dl = dl - (dh - s);
    float d2 = dh * dh;
    dd sd; sd.hi = dh;   sd.lo = fmaf(d2 * dh, -(1.0f/6.0f), dl);
    dd cd; cd.hi = 1.0f; cd.lo = -0.5f * d2;
    unsigned k = ((unsigned)(-m)) & 2047u;
    ddc w;
    if (k < 1024u) w = tw[k];
    else           w = cneg(tw[k - 1024u]);
    ddc r;
    r.re = psub(pmul(w.re, cd), pmul(w.im, sd));
    r.im = padd(pmul(w.re, sd), pmul(w.im, cd));
    return r;
}

// --------------------- fast atan2 (max err ~2e-5 rad) -----------------------
__device__ __forceinline__ float fast_atan2(float y, float x) {
    float ax = fabsf(x), ay = fabsf(y);
    float mx = fmaxf(ax, ay), mn = fminf(ax, ay);
    float t  = (mx > 0.0f) ? __fdividef(mn, mx) : 0.0f;
    float t2 = t * t;
    float p = -0.01172120f;
    p = fmaf(p, t2,  0.05265332f);
    p = fmaf(p, t2, -0.11643287f);
    p = fmaf(p, t2,  0.19354346f);
    p = fmaf(p, t2, -0.33262347f);
    p = fmaf(p, t2,  0.99997726f);
    float r = p * t;
    if (ay > ax)  r = 1.57079632679489662f - r;
    if (x < 0.0f) r = 3.14159265358979323f - r;
    return copysignf(r, y);
}

// ------------------------------ smem addressing -----------------------------
__device__ __forceinline__ int XS(int i) { return i ^ ((i >> 3) & 7); }
#define BUFSZ 2048

// reversed-address -> true frequency: a = 4g+f holds S[512f + h(g)]
__device__ __forceinline__ int freq_of(int a) {
    const int g = a >> 2, f = a & 3;
    return 512 * f + 64 * (g & 7) + 8 * ((g >> 3) & 7) + (g >> 6);
}

// ------------------------------ FFT primitives ------------------------------
template<int INV>
__device__ __forceinline__ ddc rotmi(ddc a) {   // fwd: *(-i)  inv: *(+i)
    ddc r;
    if (!INV) { r.re = a.im;        r.im = negdd(a.re); }
    else      { r.re = negdd(a.im); r.im = a.re; }
    return r;
}
template<int INV>
__device__ __forceinline__ ddc w81m(ddc a) {
    dd p = padd(a.re, a.im);
    dd m = psub(a.im, a.re);
    ddc r;
    if (!INV) { r.re = pmulC(p);         r.im = pmulC(m); }
    else      { r.re = negdd(pmulC(m));  r.im = pmulC(p); }
    return r;
}
template<int INV>
__device__ __forceinline__ ddc w83m(ddc a) {
    dd p = padd(a.re, a.im);
    dd m = psub(a.im, a.re);
    ddc r;
    if (!INV) { r.re = pmulC(m);         r.im = negdd(pmulC(p)); }
    else      { r.re = negdd(pmulC(p));  r.im = negdd(pmulC(m)); }
    return r;
}

template<int INV>
__device__ __forceinline__ void dft8(ddc* x) {
    ddc t0 = cadd(x[0], x[4]);
    ddc t1 = csub(x[0], x[4]);
    ddc t2 = cadd(x[2], x[6]);
    ddc t3 = csub(x[2], x[6]);
    ddc r3 = rotmi<INV>(t3);
    ddc E0 = cadd(t0, t2);
    ddc E2 = csub(t0, t2);
    ddc E1 = cadd(t1, r3);
    ddc E3 = csub(t1, r3);
    ddc u0 = cadd(x[1], x[5]);
    ddc u1 = csub(x[1], x[5]);
    ddc u2 = cadd(x[3], x[7]);
    ddc u3 = csub(x[3], x[7]);
    ddc s3 = rotmi<INV>(u3);
    ddc O0 = cadd(u0, u2);
    ddc O2 = csub(u0, u2);
    ddc O1 = cadd(u1, s3);
    ddc O3 = csub(u1, s3);
    ddc O1r = w81m<INV>(O1);
    ddc O2r = rotmi<INV>(O2);
    ddc O3r = w83m<INV>(O3);
    x[0] = cadd(E0, O0);  x[4] = csub(E0, O0);
    x[1] = cadd(E1, O1r); x[5] = csub(E1, O1r);
    x[2] = cadd(E2, O2r); x[6] = csub(E2, O2r);
    x[3] = cadd(E3, O3r); x[7] = csub(E3, O3r);
}

// stage-1 twiddles: 1024 table + wrap negation; INV via conj multiply
// (conj commutes with the wrap sign, so cmulc_conj(x, +/-tw) is exact).
template<int INV>
__device__ __forceinline__ void tw_apply1(ddc* x, const ddc* __restrict__ tw, int tt) {
    int idx = 0;
    #pragma unroll
    for (int j = 1; j < 8; ++j) {
        idx += tt;
        ddc w = (idx < 1024) ? tw[idx] : cneg(tw[idx - 1024]);
        x[j] = INV ? cmulc_conj(x[j], w) : cmulc(x[j], w);
    }
}
// stage-2/3 twiddles: dedicated swizzled table; INV via conj multiply
template<int INV, int BASE>
__device__ __forceinline__ void tw_apply23(ddc* x, const ddc* __restrict__ tw23, int t) {
    #pragma unroll
    for (int j = 1; j < 8; ++j) {
        ddc w = tw23[BASE + XS(t * 8 + j)];
        x[j] = INV ? cmulc_conj(x[j], w) : cmulc(x[j], w);
    }
}

// Forward DIF stages 1-3, IN-PLACE in A (XS-swizzled addresses).
__device__ __forceinline__ void fwd_stages123(ddc* x, const ddc* __restrict__ tw,
                                              const ddc* __restrict__ tw23,
                                              ddc* A, int tt) {
    dft8<0>(x);
    tw_apply1<0>(x, tw, tt);
    #pragma unroll
    for (int j = 0; j < 8; ++j) A[XS(j * 256 + tt)] = x[j];
    __syncthreads();                    // inter-warp exchange

    const int j1 = tt >> 5, t2 = tt & 31;
    #pragma unroll
    for (int k = 0; k < 8; ++k) x[k] = A[XS(j1 * 256 + t2 + 32 * k)];
    dft8<0>(x);
    tw_apply23<0, 0>(x, tw23, t2);
    #pragma unroll
    for (int j = 0; j < 8; ++j) A[XS(j1 * 256 + j * 32 + t2)] = x[j];
    __syncwarp();                       // intra-warp exchange

    const int j2 = (tt >> 2) & 7, t3 = tt & 3;
    #pragma unroll
    for (int k = 0; k < 8; ++k) x[k] = A[XS(j1 * 256 + j2 * 32 + t3 + 4 * k)];
    dft8<0>(x);
    tw_apply23<0, 256>(x, tw23, t3);
    #pragma unroll
    for (int j = 0; j < 8; ++j) A[XS(j1 * 256 + j2 * 32 + j * 4 + t3)] = x[j];
    __syncwarp();                       // intra-warp exchange
}

// Transposed-DIT inverse stages 3',2',1', IN-PLACE in A.
__device__ __forceinline__ void inv_stages321(ddc* x, const ddc* __restrict__ tw,
                                              const ddc* __restrict__ tw23,
                                              ddc* A, int tt) {
    const int j1 = tt >> 5, t2 = tt & 31;
    const int j2 = (tt >> 2) & 7, t3 = tt & 3;

    #pragma unroll
    for (int j = 0; j < 8; ++j) x[j] = A[XS(j1 * 256 + j2 * 32 + 4 * j + t3)];
    tw_apply23<1, 256>(x, tw23, t3);     // conj twiddle BEFORE butterfly
    dft8<1>(x);
    #pragma unroll
    for (int k = 0; k < 8; ++k) A[XS(j1 * 256 + j2 * 32 + t3 + 4 * k)] = x[k];
    __syncwarp();                        // intra-warp exchange

    #pragma unroll
    for (int j = 0; j < 8; ++j) x[j] = A[XS(j1 * 256 + 32 * j + t2)];
    tw_apply23<1, 0>(x, tw23, t2);
    dft8<1>(x);
    #pragma unroll
    for (int k = 0; k < 8; ++k) A[XS(j1 * 256 + t2 + 32 * k)] = x[k];
    __syncthreads();                     // inter-warp exchange

    #pragma unroll
    for (int j = 0; j < 8; ++j) x[j] = A[XS(256 * j + tt)];
    tw_apply1<1>(x, tw, tt);
    dft8<1>(x);
    // x[k] = out[tt + 256k]
}

// ------------------------------ init twiddles (merged) ----------------------
__global__ void k_init(void) {
    int e = blockIdx.x * 32 + threadIdx.x;   // 41 blocks x 32 = 1312
    if (e < 1024) {
        double s, c;
        sincospi(-(double)e / 1024.0, &s, &c);
        float ch = (float)c, cl = (float)(c - (double)ch);
        float sh = (float)s, sl = (float)(s - (double)sh);
        g_tw4[e] = make_float4(ch, cl, sh, sl);
    } else if (e < 1312) {
        int e2 = e - 1024;
        double ang;
        int slot;
        if (e2 < 256) {          // stage 2: w = exp(-2pi*i*(8*t2*j)/2048)
            int t2 = e2 >> 3, j = e2 & 7;
            ang  = (double)(t2 * j) / 128.0;
            slot = XS(e2);
        } else {                 // stage 3: w = exp(-2pi*i*(64*t3*j)/2048)
            int e3 = e2 - 256;
            int t3 = e3 >> 3, j = e3 & 7;
            ang  = (double)(t3 * j) / 16.0;
            slot = 256 + XS(e3);
        }
        double s, c;
        sincospi(-ang, &s, &c);
        float ch = (float)c, cl = (float)(c - (double)ch);
        float sh = (float)s, sl = (float)(s - (double)sh);
        g_tw23[slot] = make_float4(ch, cl, sh, sl);
    }
}

// --------------------------- shared tw staging ------------------------------
__device__ __forceinline__ void stage_tw(ddc* tw, ddc* tw23, int tt) {
    #pragma unroll
    for (int i = tt; i < 1024; i += 256) tw[i] = f4_to_ddc(g_tw4[i]);
    if (tt < 32)  tw23[256 + tt] = f4_to_ddc(g_tw23[256 + tt]);
    if (tt < 256) tw23[tt]       = f4_to_ddc(g_tw23[tt]);
}

// --------------------------- Kernel 1: rows forward (DIF) -------------------
__global__ void __launch_bounds__(256, 3)
k_fwd_rows(const float* __restrict__ amp,
           const float* __restrict__ phs,
           const float* __restrict__ aper) {
    extern __shared__ ddc sh[];
    ddc* tw   = sh;              // 1024
    ddc* tw23 = sh + 1024;       // 288
    ddc* A    = sh + 1024 + 288; // BUFSZ

    const int tt  = threadIdx.x;
    const int row = blockIdx.x & (NF - 1);
    const int img = blockIdx.x >> L2N;
    const size_t base = (size_t)img * IMG_ELEMS + ((size_t)row << L2N);

    // coalesced input prefetch (latency overlaps tw staging + barrier)
    float av[8], pv[8];
    #pragma unroll
    for (int k = 0; k < 8; ++k) {
        const int i = tt + 256 * k;
        av[k] = __fmul_rn(amp[base + i], aper[((size_t)row << L2N) + i]);
        pv[k] = phs[base + i];
    }

    stage_tw(tw, tw23, tt);
    __syncthreads();

    ddc x[8];
    #pragma unroll
    for (int k = 0; k < 8; ++k) {
        ddc e = psincos(pv[k], tw);
        x[k].re = pmuls(e.re, av[k]);
        x[k].im = pmuls(e.im, av[k]);
    }

    fwd_stages123(x, tw, tw23, A, tt);

    // stage 4 in registers, direct coalesced write in reversed order
    #pragma unroll
    for (int gg = 0; gg < 2; ++gg) {
        const int g = 2 * tt + gg;
        ddc a = A[XS(4 * g + 0)];
        ddc b = A[XS(4 * g + 1)];
        ddc c = A[XS(4 * g + 2)];
        ddc d = A[XS(4 * g + 3)];
        ddc t0 = cadd(a, c), t1 = csub(a, c);
        ddc t2 = cadd(b, d), t3 = csub(b, d);
        ddc r  = rotmi<0>(t3);
        g_spec[base + 4 * g + 0] = ddc_to_f4(cadd(t0, t2));
        g_spec[base + 4 * g + 1] = ddc_to_f4(cadd(t1, r));
        g_spec[base + 4 * g + 2] = ddc_to_f4(csub(t0, t2));
        g_spec[base + 4 * g + 3] = ddc_to_f4(csub(t1, r));
    }
}

// ------------------- Kernel 2: cols DIF + H + transposed-DIT ----------------
// (identical structure to R14 — loads AFTER the staging barrier)
__global__ void __launch_bounds__(256, 3)
k_cols() {
    extern __shared__ ddc sh[];
    ddc* tw   = sh;
    ddc* tw23 = sh + 1024;
    ddc* A    = sh + 1024 + 288;

    const int tt  = threadIdx.x;
    const int img = blockIdx.x >> L2N;
    const int col = blockIdx.x & (NF - 1);   // ADDRESS in permuted-x layout
    const size_t ibase = (size_t)img * IMG_ELEMS;

    stage_tw(tw, tw23, tt);
    __syncthreads();

    ddc x[8];
    #pragma unroll
    for (int k = 0; k < 8; ++k)
        x[k] = f4_to_ddc(g_spec[ibase + ((size_t)(tt + 256 * k) << L2N) + col]);

    fwd_stages123(x, tw, tw23, A, tt);

    // ---- stage 4 fwd + H + stage 4' inverse, in registers (own-warp cells) ----
    const int   w    = img >> 1;
    const float lam  = c_lam[w];
    const float lam2 = __fmul_rn(lam, lam);
    const float cov  = __fdiv_rn(6.283185307179586f, lam);
    const float DF   = 488.28125f;
    const int   cfr  = freq_of(col);                 // true kx frequency
    const int   kx   = (cfr < 1024) ? cfr : cfr - 2048;
    const float fx   = (float)kx * DF;
    const float fx2  = __fmul_rn(fx, fx);

    #pragma unroll
    for (int gg = 0; gg < 2; ++gg) {
        const int g = 2 * tt + gg;
        const int h = 64 * (g & 7) + 8 * ((g >> 3) & 7) + (g >> 6);
        ddc a = A[XS(4 * g + 0)];
        ddc b = A[XS(4 * g + 1)];
        ddc c = A[XS(4 * g + 2)];
        ddc d = A[XS(4 * g + 3)];
        ddc t0 = cadd(a, c), t1 = csub(a, c);
        ddc t2 = cadd(b, d), t3 = csub(b, d);
        ddc r  = rotmi<0>(t3);
        ddc F[4];
        F[0] = cadd(t0, t2);
        F[1] = cadd(t1, r);
        F[2] = csub(t0, t2);
        F[3] = csub(t1, r);
        #pragma unroll
        for (int f = 0; f < 4; ++f) {
            const int m  = 512 * f + h;
            const int ky = (m < 1024) ? m : m - 2048;
            const float fy  = (float)ky * DF;
            const float f2  = __fadd_rn(__fmul_rn(fy, fy), fx2);
            const float arg = __fsub_rn(1.0f, __fmul_rn(lam2, f2));
            if (arg > 0.0f) {
                const float kz = __fmul_rn(cov, __fsqrt_rn(arg));
                const float ph = __fmul_rn(kz, 1.0e-3f);
                ddc H = psincos(ph, tw);
                F[f] = cmulc(F[f], H);
            } else {
                F[f].re.hi = F[f].re.lo = F[f].im.hi = F[f].im.lo = 0.0f;
            }
        }
        // inverse radix-4 (stage 4'), write back to the SAME cells
        ddc s0 = cadd(F[0], F[2]), s1 = csub(F[0], F[2]);
        ddc s2 = cadd(F[1], F[3]), s3 = csub(F[1], F[3]);
        ddc ri = rotmi<1>(s3);
        A[XS(4 * g + 0)] = cadd(s0, s2);
        A[XS(4 * g + 1)] = cadd(s1, ri);
        A[XS(4 * g + 2)] = csub(s0, s2);
        A[XS(4 * g + 3)] = csub(s1, ri);
    }
    __syncwarp();                       // H-stage exchange is intra-warp

    inv_stages321(x, tw, tw23, A, tt);

    #pragma unroll
    for (int k = 0; k < 8; ++k)
        g_spec[ibase + ((size_t)(tt + 256 * k) << L2N) + col] = ddc_to_f4(x[k]);
}

// --------------------------- Kernel 3: rows inverse (DIT) -------------------
__global__ void __launch_bounds__(256, 3)
k_inv_rows(float* __restrict__ out) {
    extern __shared__ ddc sh[];
    ddc* tw   = sh;
    ddc* tw23 = sh + 1024;
    ddc* A    = sh + 1024 + 288;

    const int tt  = threadIdx.x;
    const int row = blockIdx.x & (NF - 1);
    const int img = blockIdx.x >> L2N;
    const size_t base = (size_t)img * IMG_ELEMS + ((size_t)row << L2N);

    // coalesced spectrum prefetch (8tt..8tt+7) before tw staging
    float4 Fv[8];
    #pragma unroll
    for (int q = 0; q < 8; ++q) Fv[q] = g_spec[base + 8 * tt + q];

    stage_tw(tw, tw23, tt);
    __syncthreads();

    // stage 4' : inv radix-4 on the prefetched reversed-order spectrum
    #pragma unroll
    for (int gg = 0; gg < 2; ++gg) {
        const int g = 2 * tt + gg;
        ddc F0 = f4_to_ddc(Fv[4 * gg + 0]);
        ddc F1 = f4_to_ddc(Fv[4 * gg + 1]);
        ddc F2 = f4_to_ddc(Fv[4 * gg + 2]);
        ddc F3 = f4_to_ddc(Fv[4 * gg + 3]);
        ddc s0 = cadd(F0, F2), s1 = csub(F0, F2);
        ddc s2 = cadd(F1, F3), s3 = csub(F1, F3);
        ddc ri = rotmi<1>(s3);
        A[XS(4 * g + 0)] = cadd(s0, s2);
        A[XS(4 * g + 1)] = cadd(s1, ri);
        A[XS(4 * g + 2)] = csub(s0, s2);
        A[XS(4 * g + 3)] = csub(s1, ri);
    }
    __syncwarp();

    ddc x[8];
    inv_stages321(x, tw, tw23, A, tt);

    const float sc = 1.0f / 4194304.0f;   // 1/N^2 = 2^-22 exact
    #pragma unroll
    for (int k = 0; k < 8; ++k) {
        const int n = tt + 256 * k;
        ddc v = x[k];
        float re = (v.re.hi + v.re.lo) * sc;
        float im = (v.im.hi + v.im.lo) * sc;
        out[base + n] = __fsqrt_rn(re * re + im * im);
        float ang;
        if (re < -1.0e-6f && fabsf(im) < 1.0e-6f) {
            ang = erff(im * 1.2627e7f) * 3.14159274f;  // soft +/-pi decision
        } else {
            ang = fast_atan2(im, re);
        }
        out[OUT_HALF + base + n] = ang;
    }
}

// ---------------------------------------------------------------------------
extern "C" void kernel_launch(void* const* d_in, const int* in_sizes, int n_in,
                              void* d_out, int out_size) {
    const float* amp = (const float*)d_in[0];
    const float* phs = (const float*)d_in[1];
    const float* ap  = (const float*)d_in[2];
    float* out = (float*)d_out;

    const int smem_sz = (1024 + 288 + BUFSZ) * (int)sizeof(ddc);   // 53760 B
    cudaFuncSetAttribute(k_fwd_rows, cudaFuncAttributeMaxDynamicSharedMemorySize, smem_sz);
    cudaFuncSetAttribute(k_cols,     cudaFuncAttributeMaxDynamicSharedMemorySize, smem_sz);
    cudaFuncSetAttribute(k_inv_rows, cudaFuncAttributeMaxDynamicSharedMemorySize, smem_sz);

    k_init<<<41, 32>>>();
    k_fwd_rows<<<NIMG * NF, 256, smem_sz>>>(amp, phs, ap);
    k_cols<<<NIMG * NF, 256, smem_sz>>>();
    k_inv_rows<<<NIMG * NF, 256, smem_sz>>>(out);
}

// round 17
// speedup vs baseline: 1.2068x; 1.0122x over previous
#include <cuda_runtime.h>
#include <math.h>

// ---------------------------------------------------------------------------
// Angular spectrum propagation, W=3, B=2, N=2048, double-float (f32 pair).
// R17: transposed inter-kernel layout — all strided global traffic moved to
// WRITES (fire-and-forget) so every kernel's LOADS are coalesced:
//   K1 row-FFT -> writes spectrum transposed  g_spec[a*2048 + row]
//   K2 col-FFT reads contiguous column (prefetched!), writes transposed back
//      g_spec2[n*2048 + col]
//   K3 reads g_spec2 row-major coalesced (prefetched).
// Arithmetic identical to R16 (bit-identical output): Dekker fast2sum dd,
// XS swizzle, swizzled tw23, cmulc_conj inverses, warp-local barriers,
// bit-matched f32 H args, fast_atan2 epilogue, soft +/-pi decision.
// ---------------------------------------------------------------------------

#define NF    2048
#define L2N   11
#define NIMG  6
#define IMG_ELEMS ((size_t)NF * NF)
#define OUT_HALF ((size_t)NIMG * NF * NF)

static __device__ float4 g_spec [(size_t)NIMG * NF * NF];   // [img][a][row]
static __device__ float4 g_spec2[(size_t)NIMG * NF * NF];   // [img][row][a]
static __device__ float4 g_tw4[1024];
static __device__ float4 g_tw23[288];   // [0,256): stage-2  [256,288): stage-3

__constant__ float c_lam[3] = {4.0e-7f, 5.32e-7f, 7.0e-7f};

// ------------------------------ pair arithmetic ----------------------------
struct __align__(8)  dd  { float hi, lo; };
struct __align__(16) ddc { dd re, im; };

__device__ __forceinline__ dd padd(dd a, dd b) {
    float s  = a.hi + b.hi;
    float bg = (fabsf(a.hi) >= fabsf(b.hi)) ? a.hi : b.hi;
    float sm = (fabsf(a.hi) >= fabsf(b.hi)) ? b.hi : a.hi;
    float e  = sm - (s - bg);
    dd r; r.hi = s; r.lo = e + (a.lo + b.lo); return r;
}
__device__ __forceinline__ dd psub(dd a, dd b) {
    float nbh = -b.hi;
    float s  = a.hi + nbh;
    float bg = (fabsf(a.hi) >= fabsf(nbh)) ? a.hi : nbh;
    float sm = (fabsf(a.hi) >= fabsf(nbh)) ? nbh : a.hi;
    float e  = sm - (s - bg);
    dd r; r.hi = s; r.lo = e + (a.lo - b.lo); return r;
}
__device__ __forceinline__ dd pmul(dd a, dd b) {
    float p = a.hi * b.hi;
    float e = fmaf(a.hi, b.hi, -p);
    e = fmaf(a.hi, b.lo, e);
    e = fmaf(a.lo, b.hi, e);
    dd r; r.hi = p; r.lo = e; return r;
}
__device__ __forceinline__ dd pmuls(dd a, float s) {
    float p = a.hi * s;
    float e = fmaf(a.hi, s, -p);
    e = fmaf(a.lo, s, e);
    dd r; r.hi = p; r.lo = e; return r;
}
__device__ __forceinline__ dd negdd(dd a) { dd r; r.hi = -a.hi; r.lo = -a.lo; return r; }

__device__ __forceinline__ ddc cadd(ddc a, ddc b) { ddc r; r.re = padd(a.re,b.re); r.im = padd(a.im,b.im); return r; }
__device__ __forceinline__ ddc csub(ddc a, ddc b) { ddc r; r.re = psub(a.re,b.re); r.im = psub(a.im,b.im); return r; }
__device__ __forceinline__ ddc cmulc(ddc a, ddc b) {        // a * b
    ddc r;
    r.re = psub(pmul(a.re,b.re), pmul(a.im,b.im));
    r.im = padd(pmul(a.re,b.im), pmul(a.im,b.re));
    return r;
}
__device__ __forceinline__ ddc cmulc_conj(ddc a, ddc b) {   // a * conj(b)
    ddc r;
    r.re = padd(pmul(a.re,b.re), pmul(a.im,b.im));
    r.im = psub(pmul(a.im,b.re), pmul(a.re,b.im));
    return r;
}
__device__ __forceinline__ ddc cneg(ddc a) { ddc r; r.re = negdd(a.re); r.im = negdd(a.im); return r; }
__device__ __forceinline__ ddc f4_to_ddc(float4 v) { ddc r; r.re.hi=v.x; r.re.lo=v.y; r.im.hi=v.z; r.im.lo=v.w; return r; }
__device__ __forceinline__ float4 ddc_to_f4(ddc v) { return make_float4(v.re.hi, v.re.lo, v.im.hi, v.im.lo); }

// sqrt(2)/2 as a dd constant
#define RT2H 0.70710678118654752440f
#define RT2L 1.2101617104e-08f
__device__ __forceinline__ dd pmulC(dd a) {
    dd c; c.hi = RT2H; c.lo = RT2L;
    return pmul(a, c);
}

// ------------------- pair-precision exp(+i*ph) for f32 ph -------------------
__device__ __forceinline__ ddc psincos(float ph, const ddc* __restrict__ tw) {
    const float PH_ = (float)(M_PI / 1024.0);
    const float PL_ = (float)(M_PI / 1024.0 - (double)((float)(M_PI / 1024.0)));
    int   m  = __float2int_rn(ph * 325.9493234522017f);   // 1024/pi
    float fm = (float)m;
    float th = fm * PH_;
    float te = fmaf(fm, PH_, -th);
    float tl = fmaf(fm, PL_, te);
    float s  = ph - th;
    float bb = s - ph;
    float e  = (ph - (s - bb)) + ((-th) - bb);
    float dl = e - tl;
    float dh = s + dl;
    dl = dl - (dh - s);
    float d2 = dh * dh;
    dd sd; sd.hi = dh;   sd.lo = fmaf(d2 * dh, -(1.0f/6.0f), dl);
    dd cd; cd.hi = 1.0f; cd.lo = -0.5f * d2;
    unsigned k = ((unsigned)(-m)) & 2047u;
    ddc w;
    if (k < 1024u) w = tw[k];
    else           w = cneg(tw[k - 1024u]);
    ddc r;
    r.re = psub(pmul(w.re, cd), pmul(w.im, sd));
    r.im = padd(pmul(w.re, sd), pmul(w.im, cd));
    return r;
}

// --------------------- fast atan2 (max err ~2e-5 rad) -----------------------
__device__ __forceinline__ float fast_atan2(float y, float x) {
    float ax = fabsf(x), ay = fabsf(y);
    float mx = fmaxf(ax, ay), mn = fminf(ax, ay);
    float t  = (mx > 0.0f) ? __fdividef(mn, mx) : 0.0f;
    float t2 = t * t;
    float p = -0.01172120f;
    p = fmaf(p, t2,  0.05265332f);
    p = fmaf(p, t2, -0.11643287f);
    p = fmaf(p, t2,  0.19354346f);
    p = fmaf(p, t2, -0.33262347f);
    p = fmaf(p, t2,  0.99997726f);
    float r = p * t;
    if (ay > ax)  r = 1.57079632679489662f - r;
    if (x < 0.0f) r = 3.14159265358979323f - r;
    return copysignf(r, y);
}

// ------------------------------ smem addressing -----------------------------
__device__ __forceinline__ int XS(int i) { return i ^ ((i >> 3) & 7); }
#define BUFSZ 2048

// reversed-address -> true frequency: a = 4g+f holds S[512f + h(g)]
__device__ __forceinline__ int freq_of(int a) {
    const int g = a >> 2, f = a & 3;
    return 512 * f + 64 * (g & 7) + 8 * ((g >> 3) & 7) + (g >> 6);
}

// ------------------------------ FFT primitives ------------------------------
template<int INV>
__device__ __forceinline__ ddc rotmi(ddc a) {   // fwd: *(-i)  inv: *(+i)
    ddc r;
    if (!INV) { r.re = a.im;        r.im = negdd(a.re); }
    else      { r.re = negdd(a.im); r.im = a.re; }
    return r;
}
template<int INV>
__device__ __forceinline__ ddc w81m(ddc a) {
    dd p = padd(a.re, a.im);
    dd m = psub(a.im, a.re);
    ddc r;
    if (!INV) { r.re = pmulC(p);         r.im = pmulC(m); }
    else      { r.re = negdd(pmulC(m));  r.im = pmulC(p); }
    return r;
}
template<int INV>
__device__ __forceinline__ ddc w83m(ddc a) {
    dd p = padd(a.re, a.im);
    dd m = psub(a.im, a.re);
    ddc r;
    if (!INV) { r.re = pmulC(m);         r.im = negdd(pmulC(p)); }
    else      { r.re = negdd(pmulC(p));  r.im = negdd(pmulC(m)); }
    return r;
}

template<int INV>
__device__ __forceinline__ void dft8(ddc* x) {
    ddc t0 = cadd(x[0], x[4]);
    ddc t1 = csub(x[0], x[4]);
    ddc t2 = cadd(x[2], x[6]);
    ddc t3 = csub(x[2], x[6]);
    ddc r3 = rotmi<INV>(t3);
    ddc E0 = cadd(t0, t2);
    ddc E2 = csub(t0, t2);
    ddc E1 = cadd(t1, r3);
    ddc E3 = csub(t1, r3);
    ddc u0 = cadd(x[1], x[5]);
    ddc u1 = csub(x[1], x[5]);
    ddc u2 = cadd(x[3], x[7]);
    ddc u3 = csub(x[3], x[7]);
    ddc s3 = rotmi<INV>(u3);
    ddc O0 = cadd(u0, u2);
    ddc O2 = csub(u0, u2);
    ddc O1 = cadd(u1, s3);
    ddc O3 = csub(u1, s3);
    ddc O1r = w81m<INV>(O1);
    ddc O2r = rotmi<INV>(O2);
    ddc O3r = w83m<INV>(O3);
    x[0] = cadd(E0, O0);  x[4] = csub(E0, O0);
    x[1] = cadd(E1, O1r); x[5] = csub(E1, O1r);
    x[2] = cadd(E2, O2r); x[6] = csub(E2, O2r);
    x[3] = cadd(E3, O3r); x[7] = csub(E3, O3r);
}

// stage-1 twiddles: 1024 table + wrap negation; INV via conj multiply
template<int INV>
__device__ __forceinline__ void tw_apply1(ddc* x, const ddc* __restrict__ tw, int tt) {
    int idx = 0;
    #pragma unroll
    for (int j = 1; j < 8; ++j) {
        idx += tt;
        ddc w = (idx < 1024) ? tw[idx] : cneg(tw[idx - 1024]);
        x[j] = INV ? cmulc_conj(x[j], w) : cmulc(x[j], w);
    }
}
// stage-2/3 twiddles: dedicated swizzled table; INV via conj multiply
template<int INV, int BASE>
__device__ __forceinline__ void tw_apply23(ddc* x, const ddc* __restrict__ tw23, int t) {
    #pragma unroll
    for (int j = 1; j < 8; ++j) {
        ddc w = tw23[BASE + XS(t * 8 + j)];
        x[j] = INV ? cmulc_conj(x[j], w) : cmulc(x[j], w);
    }
}

// Forward DIF stages 1-3, IN-PLACE in A (XS-swizzled addresses).
__device__ __forceinline__ void fwd_stages123(ddc* x, const ddc* __restrict__ tw,
                                              const ddc* __restrict__ tw23,
                                              ddc* A, int tt) {
    dft8<0>(x);
    tw_apply1<0>(x, tw, tt);
    #pragma unroll
    for (int j = 0; j < 8; ++j) A[XS(j * 256 + tt)] = x[j];
    __syncthreads();                    // inter-warp exchange

    const int j1 = tt >> 5, t2 = tt & 31;
    #pragma unroll
    for (int k = 0; k < 8; ++k) x[k] = A[XS(j1 * 256 + t2 + 32 * k)];
    dft8<0>(x);
    tw_apply23<0, 0>(x, tw23, t2);
    #pragma unroll
    for (int j = 0; j < 8; ++j) A[XS(j1 * 256 + j * 32 + t2)] = x[j];
    __syncwarp();                       // intra-warp exchange

    const int j2 = (tt >> 2) & 7, t3 = tt & 3;
    #pragma unroll
    for (int k = 0; k < 8; ++k) x[k] = A[XS(j1 * 256 + j2 * 32 + t3 + 4 * k)];
    dft8<0>(x);
    tw_apply23<0, 256>(x, tw23, t3);
    #pragma unroll
    for (int j = 0; j < 8; ++j) A[XS(j1 * 256 + j2 * 32 + j * 4 + t3)] = x[j];
    __syncwarp();                       // intra-warp exchange
}

// Transposed-DIT inverse stages 3',2',1', IN-PLACE in A.
__device__ __forceinline__ void inv_stages321(ddc* x, const ddc* __restrict__ tw,
                                              const ddc* __restrict__ tw23,
                                              ddc* A, int tt) {
    const int j1 = tt >> 5, t2 = tt & 31;
    const int j2 = (tt >> 2) & 7, t3 = tt & 3;

    #pragma unroll
    for (int j = 0; j < 8; ++j) x[j] = A[XS(j1 * 256 + j2 * 32 + 4 * j + t3)];
    tw_apply23<1, 256>(x, tw23, t3);     // conj twiddle BEFORE butterfly
    dft8<1>(x);
    #pragma unroll
    for (int k = 0; k < 8; ++k) A[XS(j1 * 256 + j2 * 32 + t3 + 4 * k)] = x[k];
    __syncwarp();                        // intra-warp exchange

    #pragma unroll
    for (int j = 0; j < 8; ++j) x[j] = A[XS(j1 * 256 + 32 * j + t2)];
    tw_apply23<1, 0>(x, tw23, t2);
    dft8<1>(x);
    #pragma unroll
    for (int k = 0; k < 8; ++k) A[XS(j1 * 256 + t2 + 32 * k)] = x[k];
    __syncthreads();                     // inter-warp exchange

    #pragma unroll
    for (int j = 0; j < 8; ++j) x[j] = A[XS(256 * j + tt)];
    tw_apply1<1>(x, tw, tt);
    dft8<1>(x);
    // x[k] = out[tt + 256k]
}

// ------------------------------ init twiddles (merged) ----------------------
__global__ void k_init(void) {
    int e = blockIdx.x * 32 + threadIdx.x;   // 41 blocks x 32 = 1312
    if (e < 1024) {
        double s, c;
        sincospi(-(double)e / 1024.0, &s, &c);
        float ch = (float)c, cl = (float)(c - (double)ch);
        float sh = (float)s, sl = (float)(s - (double)sh);
        g_tw4[e] = make_float4(ch, cl, sh, sl);
    } else if (e < 1312) {
        int e2 = e - 1024;
        double ang;
        int slot;
        if (e2 < 256) {          // stage 2: w = exp(-2pi*i*(8*t2*j)/2048)
            int t2 = e2 >> 3, j = e2 & 7;
            ang  = (double)(t2 * j) / 128.0;
            slot = XS(e2);
        } else {                 // stage 3: w = exp(-2pi*i*(64*t3*j)/2048)
            int e3 = e2 - 256;
            int t3 = e3 >> 3, j = e3 & 7;
            ang  = (double)(t3 * j) / 16.0;
            slot = 256 + XS(e3);
        }
        double s, c;
        sincospi(-ang, &s, &c);
        float ch = (float)c, cl = (float)(c - (double)ch);
        float sh = (float)s, sl = (float)(s - (double)sh);
        g_tw23[slot] = make_float4(ch, cl, sh, sl);
    }
}

// --------------------------- shared tw staging ------------------------------
__device__ __forceinline__ void stage_tw(ddc* tw, ddc* tw23, int tt) {
    #pragma unroll
    for (int i = tt; i < 1024; i += 256) tw[i] = f4_to_ddc(g_tw4[i]);
    if (tt < 32)  tw23[256 + tt] = f4_to_ddc(g_tw23[256 + tt]);
    if (tt < 256) tw23[tt]       = f4_to_ddc(g_tw23[tt]);
}

// --------------------------- Kernel 1: rows forward (DIF) -------------------
__global__ void __launch_bounds__(256, 3)
k_fwd_rows(const float* __restrict__ amp,
           const float* __restrict__ phs,
           const float* __restrict__ aper) {
    extern __shared__ ddc sh[];
    ddc* tw   = sh;              // 1024
    ddc* tw23 = sh + 1024;       // 288
    ddc* A    = sh + 1024 + 288; // BUFSZ

    const int tt  = threadIdx.x;
    const int row = blockIdx.x & (NF - 1);
    const int img = blockIdx.x >> L2N;
    const size_t inbase = (size_t)img * IMG_ELEMS + ((size_t)row << L2N);
    const size_t ibase  = (size_t)img * IMG_ELEMS;

    // coalesced input prefetch (latency overlaps tw staging + barrier)
    float av[8], pv[8];
    #pragma unroll
    for (int k = 0; k < 8; ++k) {
        const int i = tt + 256 * k;
        av[k] = __fmul_rn(amp[inbase + i], aper[((size_t)row << L2N) + i]);
        pv[k] = phs[inbase + i];
    }

    stage_tw(tw, tw23, tt);
    __syncthreads();

    ddc x[8];
    #pragma unroll
    for (int k = 0; k < 8; ++k) {
        ddc e = psincos(pv[k], tw);
        x[k].re = pmuls(e.re, av[k]);
        x[k].im = pmuls(e.im, av[k]);
    }

    fwd_stages123(x, tw, tw23, A, tt);

    // stage 4 in registers; TRANSPOSED write g_spec[a][row] (scatter = stores
    // only, no scoreboard stall)
    #pragma unroll
    for (int gg = 0; gg < 2; ++gg) {
        const int g = 2 * tt + gg;
        ddc a = A[XS(4 * g + 0)];
        ddc b = A[XS(4 * g + 1)];
        ddc c = A[XS(4 * g + 2)];
        ddc d = A[XS(4 * g + 3)];
        ddc t0 = cadd(a, c), t1 = csub(a, c);
        ddc t2 = cadd(b, d), t3 = csub(b, d);
        ddc r  = rotmi<0>(t3);
        g_spec[ibase + ((size_t)(4 * g + 0) << L2N) + row] = ddc_to_f4(cadd(t0, t2));
        g_spec[ibase + ((size_t)(4 * g + 1) << L2N) + row] = ddc_to_f4(cadd(t1, r));
        g_spec[ibase + ((size_t)(4 * g + 2) << L2N) + row] = ddc_to_f4(csub(t0, t2));
        g_spec[ibase + ((size_t)(4 * g + 3) << L2N) + row] = ddc_to_f4(csub(t1, r));
    }
}

// ------------------- Kernel 2: cols DIF + H + transposed-DIT ----------------
// Column data is CONTIGUOUS in g_spec ([col][r]) -> coalesced prefetch.
__global__ void __launch_bounds__(256, 3)
k_cols() {
    extern __shared__ ddc sh[];
    ddc* tw   = sh;
    ddc* tw23 = sh + 1024;
    ddc* A    = sh + 1024 + 288;

    const int tt  = threadIdx.x;
    const int img = blockIdx.x >> L2N;
    const int col = blockIdx.x & (NF - 1);   // ADDRESS in permuted-x layout
    const size_t ibase = (size_t)img * IMG_ELEMS;
    const size_t cbase = ibase + ((size_t)col << L2N);

    // coalesced column prefetch (contiguous in the transposed layout)
    float4 xv[8];
    #pragma unroll
    for (int k = 0; k < 8; ++k) xv[k] = g_spec[cbase + tt + 256 * k];

    stage_tw(tw, tw23, tt);
    __syncthreads();

    ddc x[8];
    #pragma unroll
    for (int k = 0; k < 8; ++k) x[k] = f4_to_ddc(xv[k]);

    fwd_stages123(x, tw, tw23, A, tt);

    // ---- stage 4 fwd + H + stage 4' inverse, in registers (own-warp cells) ----
    const int   w    = img >> 1;
    const float lam  = c_lam[w];
    const float lam2 = __fmul_rn(lam, lam);
    const float cov  = __fdiv_rn(6.283185307179586f, lam);
    const float DF   = 488.28125f;
    const int   cfr  = freq_of(col);                 // true kx frequency
    const int   kx   = (cfr < 1024) ? cfr : cfr - 2048;
    const float fx   = (float)kx * DF;
    const float fx2  = __fmul_rn(fx, fx);

    #pragma unroll
    for (int gg = 0; gg < 2; ++gg) {
        const int g = 2 * tt + gg;
        const int h = 64 * (g & 7) + 8 * ((g >> 3) & 7) + (g >> 6);
        ddc a = A[XS(4 * g + 0)];
        ddc b = A[XS(4 * g + 1)];
        ddc c = A[XS(4 * g + 2)];
        ddc d = A[XS(4 * g + 3)];
        ddc t0 = cadd(a, c), t1 = csub(a, c);
        ddc t2 = cadd(b, d), t3 = csub(b, d);
        ddc r  = rotmi<0>(t3);
        ddc F[4];
        F[0] = cadd(t0, t2);
        F[1] = cadd(t1, r);
        F[2] = csub(t0, t2);
        F[3] = csub(t1, r);
        #pragma unroll
        for (int f = 0; f < 4; ++f) {
            const int m  = 512 * f + h;
            const int ky = (m < 1024) ? m : m - 2048;
            const float fy  = (float)ky * DF;
            const float f2  = __fadd_rn(__fmul_rn(fy, fy), fx2);
            const float arg = __fsub_rn(1.0f, __fmul_rn(lam2, f2));
            if (arg > 0.0f) {
                const float kz = __fmul_rn(cov, __fsqrt_rn(arg));
                const float ph = __fmul_rn(kz, 1.0e-3f);
                ddc H = psincos(ph, tw);
                F[f] = cmulc(F[f], H);
            } else {
                F[f].re.hi = F[f].re.lo = F[f].im.hi = F[f].im.lo = 0.0f;
            }
        }
        // inverse radix-4 (stage 4'), write back to the SAME cells
        ddc s0 = cadd(F[0], F[2]), s1 = csub(F[0], F[2]);
        ddc s2 = cadd(F[1], F[3]), s3 = csub(F[1], F[3]);
        ddc ri = rotmi<1>(s3);
        A[XS(4 * g + 0)] = cadd(s0, s2);
        A[XS(4 * g + 1)] = cadd(s1, ri);
        A[XS(4 * g + 2)] = csub(s0, s2);
        A[XS(4 * g + 3)] = csub(s1, ri);
    }
    __syncwarp();                       // H-stage exchange is intra-warp

    inv_stages321(x, tw, tw23, A, tt);

    // TRANSPOSED write back to row-major g_spec2[n][col] (scatter stores)
    #pragma unroll
    for (int k = 0; k < 8; ++k)
        g_spec2[ibase + ((size_t)(tt + 256 * k) << L2N) + col] = ddc_to_f4(x[k]);
}

// --------------------------- Kernel 3: rows inverse (DIT) -------------------
__global__ void __launch_bounds__(256, 3)
k_inv_rows(float* __restrict__ out) {
    extern __shared__ ddc sh[];
    ddc* tw   = sh;
    ddc* tw23 = sh + 1024;
    ddc* A    = sh + 1024 + 288;

    const int tt  = threadIdx.x;
    const int row = blockIdx.x & (NF - 1);
    const int img = blockIdx.x >> L2N;
    const size_t base = (size_t)img * IMG_ELEMS + ((size_t)row << L2N);

    // coalesced spectrum prefetch (8tt..8tt+7) before tw staging
    float4 Fv[8];
    #pragma unroll
    for (int q = 0; q < 8; ++q) Fv[q] = g_spec2[base + 8 * tt + q];

    stage_tw(tw, tw23, tt);
    __syncthreads();

    // stage 4' : inv radix-4 on the prefetched reversed-order spectrum
    #pragma unroll
    for (int gg = 0; gg < 2; ++gg) {
        const int g = 2 * tt + gg;
        ddc F0 = f4_to_ddc(Fv[4 * gg + 0]);
        ddc F1 = f4_to_ddc(Fv[4 * gg + 1]);
        ddc F2 = f4_to_ddc(Fv[4 * gg + 2]);
        ddc F3 = f4_to_ddc(Fv[4 * gg + 3]);
        ddc s0 = cadd(F0, F2), s1 = csub(F0, F2);
        ddc s2 = cadd(F1, F3), s3 = csub(F1, F3);
        ddc ri = rotmi<1>(s3);
        A[XS(4 * g + 0)] = cadd(s0, s2);
        A[XS(4 * g + 1)] = cadd(s1, ri);
        A[XS(4 * g + 2)] = csub(s0, s2);
        A[XS(4 * g + 3)] = csub(s1, ri);
    }
    __syncwarp();

    ddc x[8];
    inv_stages321(x, tw, tw23, A, tt);

    const float sc = 1.0f / 4194304.0f;   // 1/N^2 = 2^-22 exact
    #pragma unroll
    for (int k = 0; k < 8; ++k) {
        const int n = tt + 256 * k;
        ddc v = x[k];
        float re = (v.re.hi + v.re.lo) * sc;
        float im = (v.im.hi + v.im.lo) * sc;
        out[base + n] = __fsqrt_rn(re * re + im * im);
        float ang;
        if (re < -1.0e-6f && fabsf(im) < 1.0e-6f) {
            ang = erff(im * 1.2627e7f) * 3.14159274f;  // soft +/-pi decision
        } else {
            ang = fast_atan2(im, re);
        }
        out[OUT_HALF + base + n] = ang;
    }
}

// ---------------------------------------------------------------------------
extern "C" void kernel_launch(void* const* d_in, const int* in_sizes, int n_in,
                              void* d_out, int out_size) {
    const float* amp = (const float*)d_in[0];
    const float* phs = (const float*)d_in[1];
    const float* ap  = (const float*)d_in[2];
    float* out = (float*)d_out;

    const int smem_sz = (1024 + 288 + BUFSZ) * (int)sizeof(ddc);   // 53760 B
    cudaFuncSetAttribute(k_fwd_rows, cudaFuncAttributeMaxDynamicSharedMemorySize, smem_sz);
    cudaFuncSetAttribute(k_cols,     cudaFuncAttributeMaxDynamicSharedMemorySize, smem_sz);
    cudaFuncSetAttribute(k_inv_rows, cudaFuncAttributeMaxDynamicSharedMemorySize, smem_sz);

    k_init<<<41, 32>>>();
    k_fwd_rows<<<NIMG * NF, 256, smem_sz>>>(amp, phs, ap);
    k_cols<<<NIMG * NF, 256, smem_sz>>>();
    k_inv_rows<<<NIMG * NF, 256, smem_sz>>>(out);
}